// round 12
// baseline (speedup 1.0000x reference)
#include <cuda_runtime.h>
#include <cuda_fp16.h>
#include <cstdint>

#define D     512
#define NWAY  64
#define MT    128
#define KT    64
#define NCH   (D / KT)     // 8
#define NTH   256

// ---- dynamic smem layout ----
#define A_BUF  16384                    // 128 rows x 128B (64 fp16 = one k-chunk)
#define B_BUF  8192                     // 64 k-rows x 128B (64 n fp16)
#define SM_XN2  0                       // 128 floats
#define SM_SPN  512                     // 64 floats
#define SM_SIPN 768                     // 64 floats
#define SM_A    1024                    // 2 x A_BUF = 32KB
#define SM_B    (SM_A + 2 * A_BUF)      // 33792: 2 x B_BUF = 16KB
#define SMEM_TOTAL (SM_B + 2 * B_BUF)   // 50176 bytes -> 3 CTAs/SM

// Pre-converted prototypes, fp16 [k][n] layout (for ldmatrix.trans B frags)
__device__ unsigned short g_bh[D * NWAY];
__device__ float g_pn[NWAY];
__device__ float g_ipn[NWAY];

// One block per prototype: norms + fp16 convert into [k][n] global.
__global__ void proto_prep_kernel(const float* __restrict__ p) {
    int c = blockIdx.x, t = threadIdx.x;   // 64 blocks x 128 threads
    float4 v = *(const float4*)(p + c * D + t * 4);
    float s = v.x * v.x + v.y * v.y + v.z * v.z + v.w * v.w;
    g_bh[(t * 4 + 0) * NWAY + c] = __half_as_ushort(__float2half_rn(v.x));
    g_bh[(t * 4 + 1) * NWAY + c] = __half_as_ushort(__float2half_rn(v.y));
    g_bh[(t * 4 + 2) * NWAY + c] = __half_as_ushort(__float2half_rn(v.z));
    g_bh[(t * 4 + 3) * NWAY + c] = __half_as_ushort(__float2half_rn(v.w));

    #pragma unroll
    for (int o = 16; o; o >>= 1) s += __shfl_xor_sync(0xffffffffu, s, o);
    __shared__ float ws[4];
    if ((t & 31) == 0) ws[t >> 5] = s;
    __syncthreads();
    if (t == 0) {
        float n2 = ws[0] + ws[1] + ws[2] + ws[3];
        float pn = sqrtf(n2);
        g_pn[c] = pn; g_ipn[c] = 1.0f / pn;
    }
}

// ---------------- PTX helpers (baseline sm_80+) ----------------
__device__ __forceinline__ uint32_t smem_u32(const void* p) {
    uint32_t a;
    asm("{ .reg .u64 t; cvta.to.shared.u64 t, %1; cvt.u32.u64 %0, t; }" : "=r"(a) : "l"(p));
    return a;
}
__device__ __forceinline__ void ldsm4(uint32_t* r, uint32_t addr) {
    asm volatile("ldmatrix.sync.aligned.m8n8.x4.shared.b16 {%0,%1,%2,%3}, [%4];"
                 : "=r"(r[0]), "=r"(r[1]), "=r"(r[2]), "=r"(r[3]) : "r"(addr));
}
__device__ __forceinline__ void ldsm4t(uint32_t* r, uint32_t addr) {
    asm volatile("ldmatrix.sync.aligned.m8n8.x4.trans.shared.b16 {%0,%1,%2,%3}, [%4];"
                 : "=r"(r[0]), "=r"(r[1]), "=r"(r[2]), "=r"(r[3]) : "r"(addr));
}
__device__ __forceinline__ void mma16816(float* d, const uint32_t* a, const uint32_t* b) {
    asm volatile(
        "mma.sync.aligned.m16n8k16.row.col.f32.f16.f16.f32 "
        "{%0,%1,%2,%3}, {%4,%5,%6,%7}, {%8,%9}, {%0,%1,%2,%3};"
        : "+f"(d[0]), "+f"(d[1]), "+f"(d[2]), "+f"(d[3])
        : "r"(a[0]), "r"(a[1]), "r"(a[2]), "r"(a[3]), "r"(b[0]), "r"(b[1]));
}
__device__ __forceinline__ void cp16(uint32_t saddr, const void* g) {
    asm volatile("cp.async.ca.shared.global [%0], [%1], 16;" :: "r"(saddr), "l"(g));
}
#define CP_COMMIT() asm volatile("cp.async.commit_group;" ::: "memory")
#define CP_WAIT0()  asm volatile("cp.async.wait_group 0;" ::: "memory")

// float4 -> 4 packed fp16 (rn)
__device__ __forceinline__ void cvt4h(float4 v, uint2& h) {
    asm("cvt.rn.f16x2.f32 %0, %1, %2;" : "=r"(h.x) : "f"(v.y), "f"(v.x));
    asm("cvt.rn.f16x2.f32 %0, %1, %2;" : "=r"(h.y) : "f"(v.w), "f"(v.z));
}

__global__ __launch_bounds__(NTH, 3) void cosine_hmma_kernel(
    const float* __restrict__ x, float* __restrict__ out) {

    extern __shared__ char smem[];
    const uint32_t sb = smem_u32(smem);
    const int tid  = threadIdx.x;
    const int wid  = tid >> 5;
    const int lane = tid & 31;
    const int mw   = wid & 3;         // warp m-tile (32 rows)
    const int nw   = wid >> 2;        // warp n-tile (32 cols)
    const long rowBase = (long)blockIdx.x * MT;

    float* xn2s = (float*)(smem + SM_XN2);
    float* spn  = (float*)(smem + SM_SPN);
    float* sipn = (float*)(smem + SM_SIPN);
    if (tid < NWAY) { spn[tid] = g_pn[tid]; sipn[tid] = g_ipn[tid]; }

    // ---- B chunk staging via cp.async (pre-converted fp16 [k][n]) ----
    auto stage_b = [&](int kt, int buf) {
        const char* bh = (const char*)g_bh + kt * 8192;
        uint32_t base = sb + SM_B + (uint32_t)(buf * B_BUF);
        #pragma unroll
        for (int i = 0; i < 2; i++) {
            int c = tid + i * NTH;            // uint4 index (0..511)
            int k = c >> 3, n0 = (c & 7) * 8;
            uint32_t off = (uint32_t)(k * 128 + ((2 * n0) ^ ((k & 7) * 16)));
            cp16(base + off, bh + c * 16);
        }
    };

    // ---- A staging: thread t -> row t>>1, k-half (t&1)*32 of the 64-chunk ----
    const int arow_t = tid >> 1;
    const int acol0  = (tid & 1) * 32;
    const uint32_t a_rowpart = (uint32_t)(arow_t * 128);
    const uint32_t a_sw      = (uint32_t)((arow_t & 7) * 16);
    const float* xrow = x + (rowBase + arow_t) * D + acol0;
    float na = 0.f;
    float4 va[4];

    // convert 4 float4 (16 floats = half this thread's 32-col slice) and STS.
    // NOTE: second 16B chunk differs in swizzle bit 4 -> address is o0 ^ 16
    // (o0 + 16 is WRONG for rows with a_sw bit4 set: carry into bit 5).
    auto stage_a_half = [&](const float4* v, uint32_t abuf, int h) {
        uint2 hh[4];
        #pragma unroll
        for (int i = 0; i < 4; i++) {
            na += v[i].x * v[i].x + v[i].y * v[i].y + v[i].z * v[i].z + v[i].w * v[i].w;
            cvt4h(v[i], hh[i]);
        }
        uint32_t o0 = abuf + a_rowpart + (a_sw ^ (uint32_t)((acol0 + 16 * h) * 2));
        asm volatile("st.shared.v4.b32 [%0], {%1,%2,%3,%4};" :: "r"(o0),
                     "r"(hh[0].x), "r"(hh[0].y), "r"(hh[1].x), "r"(hh[1].y));
        asm volatile("st.shared.v4.b32 [%0], {%1,%2,%3,%4};" :: "r"(o0 ^ 16u),
                     "r"(hh[2].x), "r"(hh[2].y), "r"(hh[3].x), "r"(hh[3].y));
    };

    {   // prologue: B chunk 0 + A chunk 0 into buf 0
        stage_b(0, 0);
        CP_COMMIT();
        #pragma unroll
        for (int h = 0; h < 2; h++) {
            const float4* xg = (const float4*)(xrow + 16 * h);
            #pragma unroll
            for (int i = 0; i < 4; i++) va[i] = xg[i];
            stage_a_half(va, sb + SM_A, h);
        }
        CP_WAIT0();
    }
    __syncthreads();

    // ---- per-lane ldmatrix address constants ----
    const int g = lane >> 3, j = lane & 7;
    uint32_t arow[2];
    #pragma unroll
    for (int mt = 0; mt < 2; mt++)
        arow[mt] = (uint32_t)((mw * 4 + mt * 2 + (g & 1)) * 1024 + j * 128);
    const uint32_t asw = (uint32_t)(j * 16);
    const uint32_t akh = (uint32_t)((g >> 1) * 16);
    uint32_t bfix[2];
    #pragma unroll
    for (int p = 0; p < 2; p++) {
        int nb = nw * 32 + (2 * p + (g >> 1)) * 8;
        bfix[p] = (uint32_t)((g & 1) * 1024 + j * 128 + ((j * 16) ^ (nb * 2)));
    }

    float acc[2][4][4];
    #pragma unroll
    for (int mt = 0; mt < 2; mt++)
        #pragma unroll
        for (int q = 0; q < 4; q++)
            #pragma unroll
            for (int e = 0; e < 4; e++) acc[mt][q][e] = 0.f;

    // one kk block: 4 LDSM + 8 MMA
    auto kk_block = [&](uint32_t abase, uint32_t bbase, int kk) {
        uint32_t ah[2][4], bq[4][2];
        uint32_t ac = asw ^ (akh + (uint32_t)(kk * 32));
        ldsm4(ah[0], abase + arow[0] + ac);
        ldsm4(ah[1], abase + arow[1] + ac);
        #pragma unroll
        for (int p = 0; p < 2; p++) {
            uint32_t t4[4];
            ldsm4t(t4, bbase + bfix[p] + (uint32_t)(kk * 2048));
            bq[2*p][0] = t4[0]; bq[2*p][1] = t4[1];
            bq[2*p+1][0] = t4[2]; bq[2*p+1][1] = t4[3];
        }
        #pragma unroll
        for (int mt = 0; mt < 2; mt++)
            #pragma unroll
            for (int q = 0; q < 4; q++)
                mma16816(acc[mt][q], ah[mt], bq[q]);
    };

    // ---- main loop over K chunks ----
    for (int kt = 0; kt < NCH; kt++) {
        const uint32_t abase = sb + SM_A + (uint32_t)((kt & 1) * A_BUF);
        const uint32_t bbase = sb + SM_B + (uint32_t)((kt & 1) * B_BUF);
        const uint32_t anext = sb + SM_A + (uint32_t)(((kt + 1) & 1) * A_BUF);
        const bool pre = (kt < NCH - 1);

        if (pre) {
            stage_b(kt + 1, (kt + 1) & 1);
            CP_COMMIT();
            const float4* xg = (const float4*)(xrow + (kt + 1) * KT);
            #pragma unroll
            for (int i = 0; i < 4; i++) va[i] = xg[i];   // next-chunk half 0
        }

        kk_block(abase, bbase, 0);
        kk_block(abase, bbase, 1);

        if (pre) {
            stage_a_half(va, anext, 0);                   // consume half 0
            const float4* xg = (const float4*)(xrow + (kt + 1) * KT + 16);
            #pragma unroll
            for (int i = 0; i < 4; i++) va[i] = xg[i];   // next-chunk half 1
        }

        kk_block(abase, bbase, 2);
        kk_block(abase, bbase, 3);

        if (pre) {
            stage_a_half(va, anext, 1);                   // consume half 1
            CP_WAIT0();
        }
        __syncthreads();
    }

    // ---- row norms: pair-reduce (two threads per row, adjacent lanes) ----
    {
        float s = na + __shfl_xor_sync(0xffffffffu, na, 1);
        if ((tid & 1) == 0) xn2s[arow_t] = s;
    }
    __syncthreads();

    // ---- epilogue: scale + store ----
    const int gr = lane >> 2, ci = lane & 3;
    #pragma unroll
    for (int mt = 0; mt < 2; mt++) {
        #pragma unroll
        for (int rr = 0; rr < 2; rr++) {
            int row = mw * 32 + mt * 16 + rr * 8 + gr;
            float n2 = xn2s[row];
            float invxn = rsqrtf(n2);
            float xn = n2 * invxn;
            float* og = out + (rowBase + row) * NWAY;
            #pragma unroll
            for (int q = 0; q < 4; q++) {
                int c0 = nw * 32 + q * 8 + ci * 2;
                float d0 = acc[mt][q][rr * 2 + 0];
                float d1 = acc[mt][q][rr * 2 + 1];
                float den0 = xn * spn[c0], den1 = xn * spn[c0 + 1];
                float s0 = (den0 < 1e-8f) ? 1e8f : invxn * sipn[c0];
                float s1 = (den1 < 1e-8f) ? 1e8f : invxn * sipn[c0 + 1];
                *(float2*)(og + c0) = make_float2(-d0 * s0, -d1 * s1);
            }
        }
    }
}

extern "C" void kernel_launch(void* const* d_in, const int* in_sizes, int n_in,
                              void* d_out, int out_size) {
    const float* x      = (const float*)d_in[0];
    const float* protos = (const float*)d_in[1];
    float* out          = (float*)d_out;
    int B = in_sizes[0] / D;   // 65536

    cudaFuncSetAttribute(cosine_hmma_kernel,
                         cudaFuncAttributeMaxDynamicSharedMemorySize, SMEM_TOTAL);

    proto_prep_kernel<<<NWAY, 128>>>(protos);
    cosine_hmma_kernel<<<B / MT, NTH, SMEM_TOTAL>>>(x, out);
}

// round 13
// speedup vs baseline: 1.0525x; 1.0525x over previous
#include <cuda_runtime.h>
#include <cuda_fp16.h>
#include <cstdint>

#define D     512
#define NWAY  64
#define MT    128
#define KT    64
#define NCH   (D / KT)     // 8
#define NTH   256

// ---- dynamic smem layout ----
#define A_BUF  16384                    // 128 rows x 128B (64 fp16 = one k-chunk)
#define B_RES  65536                    // full-K B: 512k x 64n fp16, blocked atoms
#define SM_XN2  0                       // 128 floats
#define SM_SPN  512                     // 64 floats
#define SM_SIPN 768                     // 64 floats
#define SM_A    1024                    // 2 x A_BUF = 32KB
#define SM_B    (SM_A + 2 * A_BUF)      // 33792
#define SMEM_TOTAL (SM_B + B_RES)       // 99328 bytes -> 2 CTAs/SM

// Pre-converted prototypes, fp16 [k][n] layout (for ldmatrix.trans B frags)
__device__ unsigned short g_bh[D * NWAY];
__device__ float g_pn[NWAY];
__device__ float g_ipn[NWAY];

// One block per prototype: norms + fp16 convert into [k][n] global.
__global__ void proto_prep_kernel(const float* __restrict__ p) {
    int c = blockIdx.x, t = threadIdx.x;   // 64 blocks x 128 threads
    float4 v = *(const float4*)(p + c * D + t * 4);
    float s = v.x * v.x + v.y * v.y + v.z * v.z + v.w * v.w;
    g_bh[(t * 4 + 0) * NWAY + c] = __half_as_ushort(__float2half_rn(v.x));
    g_bh[(t * 4 + 1) * NWAY + c] = __half_as_ushort(__float2half_rn(v.y));
    g_bh[(t * 4 + 2) * NWAY + c] = __half_as_ushort(__float2half_rn(v.z));
    g_bh[(t * 4 + 3) * NWAY + c] = __half_as_ushort(__float2half_rn(v.w));

    #pragma unroll
    for (int o = 16; o; o >>= 1) s += __shfl_xor_sync(0xffffffffu, s, o);
    __shared__ float ws[4];
    if ((t & 31) == 0) ws[t >> 5] = s;
    __syncthreads();
    if (t == 0) {
        float n2 = ws[0] + ws[1] + ws[2] + ws[3];
        float pn = sqrtf(n2);
        g_pn[c] = pn; g_ipn[c] = 1.0f / pn;
    }
}

// ---------------- PTX helpers (baseline sm_80+) ----------------
__device__ __forceinline__ uint32_t smem_u32(const void* p) {
    uint32_t a;
    asm("{ .reg .u64 t; cvta.to.shared.u64 t, %1; cvt.u32.u64 %0, t; }" : "=r"(a) : "l"(p));
    return a;
}
__device__ __forceinline__ void ldsm4(uint32_t* r, uint32_t addr) {
    asm volatile("ldmatrix.sync.aligned.m8n8.x4.shared.b16 {%0,%1,%2,%3}, [%4];"
                 : "=r"(r[0]), "=r"(r[1]), "=r"(r[2]), "=r"(r[3]) : "r"(addr));
}
__device__ __forceinline__ void ldsm4t(uint32_t* r, uint32_t addr) {
    asm volatile("ldmatrix.sync.aligned.m8n8.x4.trans.shared.b16 {%0,%1,%2,%3}, [%4];"
                 : "=r"(r[0]), "=r"(r[1]), "=r"(r[2]), "=r"(r[3]) : "r"(addr));
}
__device__ __forceinline__ void mma16816(float* d, const uint32_t* a, const uint32_t* b) {
    asm volatile(
        "mma.sync.aligned.m16n8k16.row.col.f32.f16.f16.f32 "
        "{%0,%1,%2,%3}, {%4,%5,%6,%7}, {%8,%9}, {%0,%1,%2,%3};"
        : "+f"(d[0]), "+f"(d[1]), "+f"(d[2]), "+f"(d[3])
        : "r"(a[0]), "r"(a[1]), "r"(a[2]), "r"(a[3]), "r"(b[0]), "r"(b[1]));
}
__device__ __forceinline__ void cp16(uint32_t saddr, const void* g) {
    asm volatile("cp.async.ca.shared.global [%0], [%1], 16;" :: "r"(saddr), "l"(g));
}
#define CP_COMMIT() asm volatile("cp.async.commit_group;" ::: "memory")
#define CP_WAIT0()  asm volatile("cp.async.wait_group 0;" ::: "memory")

// float4 -> 4 packed fp16 (rn)
__device__ __forceinline__ void cvt4h(float4 v, uint2& h) {
    asm("cvt.rn.f16x2.f32 %0, %1, %2;" : "=r"(h.x) : "f"(v.y), "f"(v.x));
    asm("cvt.rn.f16x2.f32 %0, %1, %2;" : "=r"(h.y) : "f"(v.w), "f"(v.z));
}

__global__ __launch_bounds__(NTH, 2) void cosine_hmma_kernel(
    const float* __restrict__ x, float* __restrict__ out) {

    extern __shared__ char smem[];
    const uint32_t sb = smem_u32(smem);
    const int tid  = threadIdx.x;
    const int wid  = tid >> 5;
    const int lane = tid & 31;
    const int mw   = wid & 3;         // warp m-tile (32 rows)
    const int nw   = wid >> 2;        // warp n-tile (32 cols)
    const long rowBase = (long)blockIdx.x * MT;

    float* xn2s = (float*)(smem + SM_XN2);
    float* spn  = (float*)(smem + SM_SPN);
    float* sipn = (float*)(smem + SM_SIPN);
    if (tid < NWAY) { spn[tid] = g_pn[tid]; sipn[tid] = g_ipn[tid]; }

    // ---- A staging: thread t -> row t>>1, k-half (t&1)*32 of the 64-chunk ----
    const int arow_t = tid >> 1;
    const int acol0  = (tid & 1) * 32;
    const uint32_t a_rowpart = (uint32_t)(arow_t * 128);
    const uint32_t a_sw      = (uint32_t)((arow_t & 7) * 16);
    float na = 0.f;
    float4 va[8];

    {   // ---- prologue: full-K B via cp.async (once) + A chunk 0 ----
        // B resident layout: atom (8k x 64n = 1024B), k 0..511 -> 64 atoms.
        // off(k, n0) = (k>>3)*1024 + (k&7)*128 + (((k&7)*16) ^ (n0*2))
        #pragma unroll
        for (int i = 0; i < 16; i++) {
            int c = tid + i * NTH;            // uint4 index (0..4095)
            int k = c >> 3, n0 = (c & 7) * 8;
            uint32_t off = (uint32_t)((k >> 3) * 1024 + (k & 7) * 128
                                      + (((k & 7) * 16) ^ (n0 * 2)));
            cp16(sb + SM_B + off, (const char*)g_bh + c * 16);
        }
        CP_COMMIT();

        const float4* xg = (const float4*)(x + (rowBase + arow_t) * D + acol0);
        #pragma unroll
        for (int i = 0; i < 8; i++) va[i] = xg[i];
        #pragma unroll
        for (int i = 0; i < 8; i++) {
            float4 v = va[i];
            na += v.x * v.x + v.y * v.y + v.z * v.z + v.w * v.w;
            uint2 h; cvt4h(v, h);
            uint32_t off = SM_A + a_rowpart + (a_sw ^ (uint32_t)((acol0 + 4 * i) * 2));
            *(uint2*)(smem + off) = h;
        }
        CP_WAIT0();
    }
    __syncthreads();

    // ---- per-lane ldmatrix address constants ----
    const int g = lane >> 3, j = lane & 7;
    uint32_t arow[2];
    #pragma unroll
    for (int mt = 0; mt < 2; mt++)
        arow[mt] = (uint32_t)((mw * 4 + mt * 2 + (g & 1)) * 1024 + j * 128);
    const uint32_t asw = (uint32_t)(j * 16);
    const uint32_t akh = (uint32_t)((g >> 1) * 16);
    uint32_t bfix[2];
    #pragma unroll
    for (int p = 0; p < 2; p++) {
        int nb = nw * 32 + (2 * p + (g >> 1)) * 8;
        bfix[p] = (uint32_t)((g & 1) * 1024 + j * 128 + ((j * 16) ^ (nb * 2)));
    }

    float acc[2][4][4];
    #pragma unroll
    for (int mt = 0; mt < 2; mt++)
        #pragma unroll
        for (int q = 0; q < 4; q++)
            #pragma unroll
            for (int e = 0; e < 4; e++) acc[mt][q][e] = 0.f;

    // ---- main loop over K chunks (B resident: no staging, no cp.async) ----
    for (int kt = 0; kt < NCH; kt++) {
        if (kt < NCH - 1) {   // full-window prefetch: issue all 8 LDG up front
            const float4* xg = (const float4*)(x + (rowBase + arow_t) * D + (kt + 1) * KT + acol0);
            #pragma unroll
            for (int i = 0; i < 8; i++) va[i] = xg[i];
        }

        const uint32_t abase = sb + SM_A + (uint32_t)((kt & 1) * A_BUF);
        const uint32_t bbase = sb + SM_B + (uint32_t)(kt * 8192);   // chunk kt = 8 atoms
        #pragma unroll
        for (int kk = 0; kk < 4; kk++) {
            uint32_t ah[2][4], bq[4][2];
            uint32_t ac = asw ^ (akh + (uint32_t)(kk * 32));
            ldsm4(ah[0], abase + arow[0] + ac);
            ldsm4(ah[1], abase + arow[1] + ac);
            #pragma unroll
            for (int p = 0; p < 2; p++) {
                uint32_t t4[4];
                ldsm4t(t4, bbase + bfix[p] + (uint32_t)(kk * 2048));
                bq[2*p][0] = t4[0]; bq[2*p][1] = t4[1];
                bq[2*p+1][0] = t4[2]; bq[2*p+1][1] = t4[3];
            }
            #pragma unroll
            for (int mt = 0; mt < 2; mt++)
                #pragma unroll
                for (int q = 0; q < 4; q++)
                    mma16816(acc[mt][q], ah[mt], bq[q]);
        }

        if (kt < NCH - 1) {   // stage A chunk kt+1 into the other buffer
            uint32_t base = SM_A + (uint32_t)(((kt + 1) & 1) * A_BUF);
            #pragma unroll
            for (int i = 0; i < 8; i++) {
                float4 v = va[i];
                na += v.x * v.x + v.y * v.y + v.z * v.z + v.w * v.w;
                uint2 h; cvt4h(v, h);
                uint32_t off = base + a_rowpart + (a_sw ^ (uint32_t)((acol0 + 4 * i) * 2));
                *(uint2*)(smem + off) = h;
            }
        }
        __syncthreads();
    }

    // ---- row norms: pair-reduce (two threads per row, adjacent lanes) ----
    {
        float s = na + __shfl_xor_sync(0xffffffffu, na, 1);
        if ((tid & 1) == 0) xn2s[arow_t] = s;
    }
    __syncthreads();

    // ---- epilogue: scale + store ----
    const int gr = lane >> 2, ci = lane & 3;
    #pragma unroll
    for (int mt = 0; mt < 2; mt++) {
        #pragma unroll
        for (int rr = 0; rr < 2; rr++) {
            int row = mw * 32 + mt * 16 + rr * 8 + gr;
            float n2 = xn2s[row];
            float invxn = rsqrtf(n2);
            float xn = n2 * invxn;
            float* og = out + (rowBase + row) * NWAY;
            #pragma unroll
            for (int q = 0; q < 4; q++) {
                int c0 = nw * 32 + q * 8 + ci * 2;
                float d0 = acc[mt][q][rr * 2 + 0];
                float d1 = acc[mt][q][rr * 2 + 1];
                float den0 = xn * spn[c0], den1 = xn * spn[c0 + 1];
                float s0 = (den0 < 1e-8f) ? 1e8f : invxn * sipn[c0];
                float s1 = (den1 < 1e-8f) ? 1e8f : invxn * sipn[c0 + 1];
                *(float2*)(og + c0) = make_float2(-d0 * s0, -d1 * s1);
            }
        }
    }
}

extern "C" void kernel_launch(void* const* d_in, const int* in_sizes, int n_in,
                              void* d_out, int out_size) {
    const float* x      = (const float*)d_in[0];
    const float* protos = (const float*)d_in[1];
    float* out          = (float*)d_out;
    int B = in_sizes[0] / D;   // 65536

    cudaFuncSetAttribute(cosine_hmma_kernel,
                         cudaFuncAttributeMaxDynamicSharedMemorySize, SMEM_TOTAL);

    proto_prep_kernel<<<NWAY, 128>>>(protos);
    cosine_hmma_kernel<<<B / MT, NTH, SMEM_TOTAL>>>(x, out);
}